// round 17
// baseline (speedup 1.0000x reference)
#include <cuda_runtime.h>
#include <cuda_bf16.h>
#include <mma.h>
#include <cstdint>

using namespace nvcuda;

#define NN    6144
#define INF   256
#define NH    4
#define DHD   64
#define HD    256
#define NCOLS 576
#define MROWS (NN + 128)     // extra m-tile: row 6144 = ones (T row), rest zeros

// GEMM tiling (round-6 warp config; 2-stage smem w/ in-GEMM int->bf16 A convert)
#define BM 128
#define BN 192
#define BK 64
#define KITERS (NN / BK)     // 96
#define GTHREADS 256

#define A_LD    72                        // bf16 elems per A row (64 + 8 pad)
#define B_LD    200                       // bf16 elems per B row (192 + 8 pad)
#define INTA_BYTES 32768                  // 128 rows x 64 int32
#define BFA_BYTES  (BM * A_LD * 2)        // 18432
#define BSTG_BYTES (2 * BK * B_LD * 2)    // 51200 (Bhi + Blo)
#define SM_INTA(s) ((s) * INTA_BYTES)
#define SM_BFA     (2 * INTA_BYTES)                        // 65536
#define SM_BH(s)   (SM_BFA + BFA_BYTES + (s) * BSTG_BYTES) // 83968 + s*51200
#define SM_BL(s)   (SM_BH(s) + BK * B_LD * 2)
#define SMEM_BYTES (SM_BFA + BFA_BYTES + 2 * BSTG_BYTES)   // 186368

// ---------------- scratch ----------------
__device__ float          g_esrc[NH][NN];
__device__ __nv_bfloat16  g_Bhi[NN][NCOLS];   // cols 517..575 never written: stay zero
__device__ __nv_bfloat16  g_Blo[NN][NCOLS];
__device__ float          g_C[MROWS][NCOLS];

// ---------------- helpers ----------------
__device__ __forceinline__ uint32_t smem_u32(const void* p) {
    uint32_t a;
    asm("{ .reg .u64 t; cvta.to.shared.u64 t, %1; cvt.u32.u64 %0, t; }" : "=r"(a) : "l"(p));
    return a;
}
__device__ __forceinline__ void cp16(uint32_t dst, const void* src) {
    asm volatile("cp.async.cg.shared.global [%0], [%1], 16;" :: "r"(dst), "l"(src) : "memory");
}
__device__ __forceinline__ uint32_t pack2(int a, int b) {
    return (a > 0 ? 0x3F80u : 0u) | ((b > 0 ? 0x3F80u : 0u) << 16);
}
__device__ __forceinline__ uint32_t packbf2(float a, float b) {
    uint32_t ua = __bfloat16_as_ushort(__float2bfloat16(a));
    uint32_t ub = __bfloat16_as_ushort(__float2bfloat16(b));
    return ua | (ub << 16);
}

// ---------------- K1: fused  h-gemm + scores + buildB (384 blocks) ----------------
#define HBLOCKS (NN / 64 * NH)     // 384

__global__ void k_pre(const float* __restrict__ x, const float* __restrict__ W,
                      const float* __restrict__ Wb, const float* __restrict__ A,
                      const float* __restrict__ Ab) {
    __shared__ float sA[16][68];
    __shared__ float sB[16][64];
    __shared__ float sps[64][17];
    __shared__ float spd[64][17];
    __shared__ float sesd[64];
    const int bx = blockIdx.x;
    const int tid = threadIdx.x;

    const int head = bx & 3;
    const int m0 = (bx >> 2) * 64;
    const int tx = tid & 15;
    const int ty = tid >> 4;

    float acc[4][4];
#pragma unroll
    for (int r = 0; r < 4; r++)
#pragma unroll
        for (int c = 0; c < 4; c++) acc[r][c] = 0.f;

    for (int k0 = 0; k0 < INF; k0 += 16) {
#pragma unroll
        for (int i = tid; i < 1024; i += 256) {
            int m = i >> 4, kk = i & 15;
            sA[kk][m] = x[(m0 + m) * INF + k0 + kk];
        }
#pragma unroll
        for (int i = tid; i < 1024; i += 256) {
            int kk = i >> 6, c = i & 63;
            sB[kk][c] = W[head * (INF * DHD) + (k0 + kk) * DHD + c];
        }
        __syncthreads();
#pragma unroll
        for (int kk = 0; kk < 16; kk++) {
            float4 av = *(const float4*)&sA[kk][ty * 4];
            float4 bv = *(const float4*)&sB[kk][tx * 4];
            float a4[4] = {av.x, av.y, av.z, av.w};
            float b4[4] = {bv.x, bv.y, bv.z, bv.w};
#pragma unroll
            for (int r = 0; r < 4; r++)
#pragma unroll
                for (int c = 0; c < 4; c++) acc[r][c] += a4[r] * b4[c];
        }
        __syncthreads();
    }

#pragma unroll
    for (int c = 0; c < 4; c++) {
        float wb = Wb[head * DHD + tx * 4 + c];
#pragma unroll
        for (int r = 0; r < 4; r++) acc[r][c] += wb;
    }

    {
        const float* Ah = A + head * 2 * DHD;
        float as[4], ad[4];
#pragma unroll
        for (int c = 0; c < 4; c++) {
            as[c] = Ah[tx * 4 + c];
            ad[c] = Ah[DHD + tx * 4 + c];
        }
#pragma unroll
        for (int r = 0; r < 4; r++) {
            float ps = 0.f, pd = 0.f;
#pragma unroll
            for (int c = 0; c < 4; c++) {
                ps += acc[r][c] * as[c];
                pd += acc[r][c] * ad[c];
            }
            sps[ty * 4 + r][tx] = ps;
            spd[ty * 4 + r][tx] = pd;
        }
    }
    __syncthreads();

    if (tid < 64) {
        float ps = 0.f, pd = 0.f;
#pragma unroll
        for (int j = 0; j < 16; j++) {
            ps += sps[tid][j];
            pd += spd[tid][j];
        }
        const float esr = expf(ps + Ab[head]);
        const float esd = expf(pd);
        const int k = m0 + tid;
        g_esrc[head][k] = esr;
        sesd[tid] = esd;
        __nv_bfloat16 dhi = __float2bfloat16(esd);
        g_Bhi[k][512 + head] = dhi;
        g_Blo[k][512 + head] = __float2bfloat16(esd - __bfloat162float(dhi));
        if (head == 0) {
            g_Bhi[k][516] = __float2bfloat16(1.0f);
            g_Blo[k][516] = __float2bfloat16(0.0f);
        }
    }
    __syncthreads();

#pragma unroll
    for (int r = 0; r < 4; r++) {
        const int k = m0 + ty * 4 + r;
        const float esd = sesd[ty * 4 + r];
        float v1[4], v2[4], l1[4], l2[4];
#pragma unroll
        for (int c = 0; c < 4; c++) {
            v2[c] = acc[r][c];
            v1[c] = esd * acc[r][c];
            l1[c] = v1[c] - __bfloat162float(__float2bfloat16(v1[c]));
            l2[c] = v2[c] - __bfloat162float(__float2bfloat16(v2[c]));
        }
        uint2 hi1 = make_uint2(packbf2(v1[0], v1[1]), packbf2(v1[2], v1[3]));
        uint2 lo1 = make_uint2(packbf2(l1[0], l1[1]), packbf2(l1[2], l1[3]));
        uint2 hi2 = make_uint2(packbf2(v2[0], v2[1]), packbf2(v2[2], v2[3]));
        uint2 lo2 = make_uint2(packbf2(l2[0], l2[1]), packbf2(l2[2], l2[3]));
        *(uint2*)&g_Bhi[k][head * 64 + tx * 4]       = hi1;
        *(uint2*)&g_Blo[k][head * 64 + tx * 4]       = lo1;
        *(uint2*)&g_Bhi[k][256 + head * 64 + tx * 4] = hi2;
        *(uint2*)&g_Blo[k][256 + head * 64 + tx * 4] = lo2;
    }
}

// ---------------- K2: pipelined wmma GEMM, A = int32 adj converted in smem ----------------
__device__ __forceinline__ void load_stage(uint32_t sb, int s, int k0, int m0, int n0,
                                           const int* __restrict__ adj, int tid) {
    // A: 128 rows x 64 int32 = 2048 16B-chunks -> 8 per thread (skip for ones-tile)
    if (m0 < NN) {
        const uint32_t a_base = sb + SM_INTA(s);
#pragma unroll
        for (int q = 0; q < 8; q++) {
            int ch = tid + q * 256;
            int row = ch >> 4, c = ch & 15;
            cp16(a_base + ch * 16, adj + (size_t)(m0 + row) * NN + k0 + c * 4);
        }
    }
    const uint32_t bh_base = sb + SM_BH(s);
    const uint32_t bl_base = sb + SM_BL(s);
#pragma unroll
    for (int q = 0; q < 6; q++) {
        int idx = tid + q * 256;
        int row = idx / 24, c = idx - row * 24;
        cp16(bh_base + row * (B_LD * 2) + c * 16, &g_Bhi[k0 + row][n0 + c * 8]);
    }
#pragma unroll
    for (int q = 0; q < 6; q++) {
        int idx = tid + q * 256;
        int row = idx / 24, c = idx - row * 24;
        cp16(bl_base + row * (B_LD * 2) + c * 16, &g_Blo[k0 + row][n0 + c * 8]);
    }
    asm volatile("cp.async.commit_group;" ::: "memory");
}

__global__ void __launch_bounds__(GTHREADS, 1) k_attn_gemm(const int* __restrict__ adj) {
    extern __shared__ char smem[];
    const uint32_t sb = smem_u32(smem);
    const int tid = threadIdx.x;
    const int wid = tid >> 5;
    const int wm = wid >> 2;          // 0..1  (64 rows each)
    const int wn = wid & 3;           // 0..3  (48 cols each)
    const int n0 = blockIdx.x * BN;
    const int m0 = blockIdx.y * BM;

    // convert mapping: thread -> (row, half-row of 32 ints)
    const int crow = tid >> 1;
    const int chalf = tid & 1;

    wmma::fragment<wmma::accumulator, 16, 16, 16, float> acc[4][3];
#pragma unroll
    for (int r = 0; r < 4; r++)
#pragma unroll
        for (int c = 0; c < 3; c++) wmma::fill_fragment(acc[r][c], 0.f);

    load_stage(sb, 0, 0, m0, n0, adj, tid);
    load_stage(sb, 1, BK, m0, n0, adj, tid);

    for (int i = 0; i < KITERS; i++) {
        const int s = i & 1;

        asm volatile("cp.async.wait_group 1;" ::: "memory");
        __syncthreads();                      // (a) stage s visible; prior MMA done (bfA free)

        // convert intA(s) -> bfA  (or constants for the ones-tile)
        if (m0 < NN) {
            const int4* ip = (const int4*)(smem + SM_INTA(s));
            char* bp = smem + SM_BFA + crow * (A_LD * 2) + chalf * 64;
            const int cbase = crow * 16 + chalf * 8;
#pragma unroll
            for (int j = 0; j < 8; j++) {
                int l = (j + tid) & 7;
                int4 a = ip[cbase + l];
                *(uint2*)(bp + l * 8) = make_uint2(pack2(a.x, a.y), pack2(a.z, a.w));
            }
        } else {
            const uint32_t v = (crow == 0) ? 0x3F803F80u : 0u;   // global row 6144 = ones
            char* bp = smem + SM_BFA + crow * (A_LD * 2) + chalf * 64;
#pragma unroll
            for (int j = 0; j < 8; j++)
                *(uint2*)(bp + j * 8) = make_uint2(v, v);
        }
        __syncthreads();                      // (b) bfA ready

        const __nv_bfloat16* sA  = (const __nv_bfloat16*)(smem + SM_BFA);
        const __nv_bfloat16* sBh = (const __nv_bfloat16*)(smem + SM_BH(s));
        const __nv_bfloat16* sBl = (const __nv_bfloat16*)(smem + SM_BL(s));

#pragma unroll
        for (int kk = 0; kk < BK / 16; kk++) {
            wmma::fragment<wmma::matrix_a, 16, 16, 16, __nv_bfloat16, wmma::row_major> af[4];
#pragma unroll
            for (int r = 0; r < 4; r++)
                wmma::load_matrix_sync(af[r], sA + (wm * 64 + r * 16) * A_LD + kk * 16, A_LD);
#pragma unroll
            for (int c = 0; c < 3; c++) {
                wmma::fragment<wmma::matrix_b, 16, 16, 16, __nv_bfloat16, wmma::row_major> bf;
                wmma::load_matrix_sync(bf, sBh + (kk * 16) * B_LD + wn * 48 + c * 16, B_LD);
#pragma unroll
                for (int r = 0; r < 4; r++) wmma::mma_sync(acc[r][c], af[r], bf, acc[r][c]);
                wmma::load_matrix_sync(bf, sBl + (kk * 16) * B_LD + wn * 48 + c * 16, B_LD);
#pragma unroll
                for (int r = 0; r < 4; r++) wmma::mma_sync(acc[r][c], af[r], bf, acc[r][c]);
            }
        }
        __syncthreads();                      // (c) stage s fully consumed -> refill

        if (i + 2 < KITERS)
            load_stage(sb, s, (i + 2) * BK, m0, n0, adj, tid);
        else
            asm volatile("cp.async.commit_group;" ::: "memory");
    }

#pragma unroll
    for (int r = 0; r < 4; r++)
#pragma unroll
        for (int c = 0; c < 3; c++)
            wmma::store_matrix_sync(&g_C[m0 + wm * 64 + r * 16][n0 + wn * 48 + c * 16],
                                    acc[r][c], NCOLS, wmma::mem_row_major);
}

// ---------------- K3: epilogue (float4; T from GEMM ones-row) ----------------
__global__ void k_epi(float* __restrict__ out) {
    const int t = blockIdx.x * 256 + threadIdx.x;
    const int n = t >> 6;
    const int c4 = (t & 63) * 4;
    const int hd = c4 >> 6;
    const float es  = g_esrc[hd][n];
    const float4 u  = *(const float4*)&g_C[n][c4];
    const float4 v  = *(const float4*)&g_C[n][256 + c4];
    const float4 T  = *(const float4*)&g_C[NN][256 + c4];
    const float w   = g_C[n][512 + hd];
    const float deg = g_C[n][516];
    const float invZ = 1.0f / (es * w + ((float)NN - deg));
    float4 o;
    o.x = (es * u.x + T.x - v.x) * invZ;
    o.y = (es * u.y + T.y - v.y) * invZ;
    o.z = (es * u.z + T.z - v.z) * invZ;
    o.w = (es * u.w + T.w - v.w) * invZ;
    *(float4*)&out[n * HD + c4] = o;
}

// ---------------- launch ----------------
extern "C" void kernel_launch(void* const* d_in, const int* in_sizes, int n_in,
                              void* d_out, int out_size) {
    const float* x = nullptr; const int* adj = nullptr;
    const float* W = nullptr; const float* Wb = nullptr;
    const float* A = nullptr; const float* Ab = nullptr;
    for (int i = 0; i < n_in; i++) {
        switch (in_sizes[i]) {
            case NN * INF:        x   = (const float*)d_in[i]; break;
            case NH * INF * DHD:  W   = (const float*)d_in[i]; break;
            case NH * DHD:        Wb  = (const float*)d_in[i]; break;
            case NH * 2 * DHD:    A   = (const float*)d_in[i]; break;
            case NH:              Ab  = (const float*)d_in[i]; break;
            default:
                if (in_sizes[i] == NN * NN) adj = (const int*)d_in[i];
                break;
        }
    }
    float* out = (float*)d_out;

    cudaFuncSetAttribute(k_attn_gemm, cudaFuncAttributeMaxDynamicSharedMemorySize, SMEM_BYTES);

    k_pre<<<HBLOCKS, 256>>>(x, W, Wb, A, Ab);
    k_attn_gemm<<<dim3(NCOLS / BN, MROWS / BM), GTHREADS, SMEM_BYTES>>>(adj);
    k_epi<<<(NN * 64) / 256, 256>>>(out);
}